// round 14
// baseline (speedup 1.0000x reference)
#include <cuda_runtime.h>

#define NUM_NODES  100000
#define NUM_GRAPHS 512
#define CAP 96                 // max in-degree slots (Poisson(16) tail: overflow ~1e-20)
#define F1 128
#define F2 64
#define BN_EPS 1e-5f

// ---------------- scratch (static device globals; no allocation) ----------------
__device__ __align__(16) int   g_cnt [NUM_NODES];          // in-degree (excl self)
__device__ __align__(16) int   g_esrc[NUM_NODES * CAP];    // bucket CSR: src ids per dst
__device__ __align__(16) float g_dis [NUM_NODES];
__device__ __align__(16) float g_xw1 [NUM_NODES * F1];     // pre-scaled by dis[row]
__device__ __align__(16) float g_acc1[NUM_NODES * F1];
__device__ __align__(16) float g_xw2 [NUM_NODES * F2];     // pre-scaled by dis[row]
__device__ __align__(16) float g_pooled[NUM_GRAPHS * F2];
__device__ __align__(16) float g_mean[F2];
__device__ __align__(16) float g_rstd[F2];

__device__ __forceinline__ void red_add_v2(float* p, float x, float y) {
    asm volatile("red.global.add.v2.f32 [%0], {%1,%2};"
                 :: "l"(p), "f"(x), "f"(y) : "memory");
}

__device__ __forceinline__ unsigned f2tf(float f) {
    unsigned u;
    asm("cvt.rna.tf32.f32 %0, %1;" : "=r"(u) : "f"(f));
    return u;
}
// split f into tf32 hi + tf32 lo (3xTF32 scheme)
__device__ __forceinline__ void tfsplit(float f, unsigned& hi, unsigned& lo) {
    hi = f2tf(f);
    lo = f2tf(f - __uint_as_float(hi));
}

__device__ __forceinline__ void mma_tf32(float4& c,
    unsigned a0, unsigned a1, unsigned a2, unsigned a3,
    unsigned b0, unsigned b1)
{
    asm volatile(
        "mma.sync.aligned.m16n8k8.row.col.f32.tf32.tf32.f32 "
        "{%0,%1,%2,%3}, {%4,%5,%6,%7}, {%8,%9}, {%0,%1,%2,%3};"
        : "+f"(c.x), "+f"(c.y), "+f"(c.z), "+f"(c.w)
        : "r"(a0), "r"(a1), "r"(a2), "r"(a3), "r"(b0), "r"(b1));
}

// -------- fused count + bucket fill: 1 edge per thread (latency-bound) -----
__global__ void k_fill2(const int* __restrict__ src, const int* __restrict__ dst, int E) {
    int e = blockIdx.x * blockDim.x + threadIdx.x;
    if (e < E) {
        int d = __ldg(&dst[e]);
        int s = __ldg(&src[e]);
        int slot = atomicAdd(&g_cnt[d], 1);
        if (slot < CAP) g_esrc[(size_t)d * CAP + slot] = s;
    }
}

// ---------------- dis = rsqrt(deg+1) ----------------
__global__ void k_dis(int n) {
    int i = blockIdx.x * blockDim.x + threadIdx.x;
    if (i < n) g_dis[i] = rsqrtf((float)(g_cnt[i] + 1));
}

// ---------------- zero pooled (kernel, not memset: keeps gemm1 at profile idx 3)
__global__ void k_zero() {
    int i = blockIdx.x * blockDim.x + threadIdx.x;
    if (i < NUM_GRAPHS * F2) g_pooled[i] = 0.0f;
}

// ---- GEMM 1 (3xTF32, double-buffered W): xw1' = (x @ W1)*dis  [N,128]x[128,128]
// dyn smem: As fp32 64x132 | Wh u32 [2][16x132] | Wl u32 [2][16x132]  (67584 B)
#define CHUNK1 (16 * 132)
#define GEMM1_SMEM ((64 * 132 + 4 * CHUNK1) * 4)
__global__ void k_gemm1(const float* __restrict__ x, const float* __restrict__ W, int n) {
    extern __shared__ unsigned char dyn[];
    float*    As = (float*)dyn;                       // 64*132
    unsigned* Wh = (unsigned*)(As + 64 * 132);        // [2][16*132]
    unsigned* Wl = Wh + 2 * CHUNK1;                   // [2][16*132]
    int tid  = threadIdx.x;
    int lane = tid & 31, warp = tid >> 5;
    int wm = (warp & 3) * 16;           // warp m-base
    int wn = (warp >> 2) * 64;          // warp n-base (0 or 64)
    int row0 = blockIdx.x * 64;
    int gid = lane >> 2, tig = lane & 3;

    const float4* x4 = (const float4*)x;
#pragma unroll
    for (int i = 0; i < 8; i++) {
        int idx = tid + i * 256;        // 0..2047 float4s
        int r = idx >> 5, c4 = idx & 31;
        int row = row0 + r;
        float4 v = (row < n) ? __ldcs(&x4[(size_t)row * 32 + c4])
                             : make_float4(0.f, 0.f, 0.f, 0.f);
        *(float4*)&As[r * 132 + c4 * 4] = v;
    }

    float4 c[8];
#pragma unroll
    for (int t = 0; t < 8; t++) c[t] = make_float4(0.f, 0.f, 0.f, 0.f);

    const float4* W4 = (const float4*)W;
    int wr = tid >> 5, wc4 = tid & 31;           // W-chunk load coords (r=wr, r+8=wr+8)

    // prologue: chunk 0 -> buf 0
    {
        float4 v0 = __ldg(&W4[(size_t)wr * 32 + wc4]);
        float4 v1 = __ldg(&W4[(size_t)(wr + 8) * 32 + wc4]);
        uint4 h, l;
        tfsplit(v0.x, h.x, l.x); tfsplit(v0.y, h.y, l.y);
        tfsplit(v0.z, h.z, l.z); tfsplit(v0.w, h.w, l.w);
        *(uint4*)&Wh[wr * 132 + wc4 * 4] = h;
        *(uint4*)&Wl[wr * 132 + wc4 * 4] = l;
        tfsplit(v1.x, h.x, l.x); tfsplit(v1.y, h.y, l.y);
        tfsplit(v1.z, h.z, l.z); tfsplit(v1.w, h.w, l.w);
        *(uint4*)&Wh[(wr + 8) * 132 + wc4 * 4] = h;
        *(uint4*)&Wl[(wr + 8) * 132 + wc4 * 4] = l;
    }
    __syncthreads();

    for (int kc = 0; kc < 8; kc++) {
        int cur = (kc & 1) * CHUNK1;
        int nxt = ((kc + 1) & 1) * CHUNK1;
        float4 v0, v1;
        if (kc < 7) {   // prefetch next chunk to regs
            v0 = __ldg(&W4[(size_t)((kc + 1) * 16 + wr) * 32 + wc4]);
            v1 = __ldg(&W4[(size_t)((kc + 1) * 16 + wr + 8) * 32 + wc4]);
        }
#pragma unroll
        for (int ks = 0; ks < 2; ks++) {
            int k0 = kc * 16 + ks * 8;
            int kk = ks * 8;
            unsigned ah[4], al[4];
            tfsplit(As[(wm + gid)     * 132 + k0 + tig],     ah[0], al[0]);
            tfsplit(As[(wm + gid + 8) * 132 + k0 + tig],     ah[1], al[1]);
            tfsplit(As[(wm + gid)     * 132 + k0 + tig + 4], ah[2], al[2]);
            tfsplit(As[(wm + gid + 8) * 132 + k0 + tig + 4], ah[3], al[3]);
#pragma unroll
            for (int t = 0; t < 8; t++) {
                int nn = wn + t * 8 + gid;
                unsigned bh0 = Wh[cur + (kk + tig)     * 132 + nn];
                unsigned bh1 = Wh[cur + (kk + tig + 4) * 132 + nn];
                unsigned bl0 = Wl[cur + (kk + tig)     * 132 + nn];
                unsigned bl1 = Wl[cur + (kk + tig + 4) * 132 + nn];
                mma_tf32(c[t], al[0], al[1], al[2], al[3], bh0, bh1);  // a_lo*b_hi
                mma_tf32(c[t], ah[0], ah[1], ah[2], ah[3], bl0, bl1);  // a_hi*b_lo
                mma_tf32(c[t], ah[0], ah[1], ah[2], ah[3], bh0, bh1);  // a_hi*b_hi
            }
        }
        if (kc < 7) {
            uint4 h, l;
            tfsplit(v0.x, h.x, l.x); tfsplit(v0.y, h.y, l.y);
            tfsplit(v0.z, h.z, l.z); tfsplit(v0.w, h.w, l.w);
            *(uint4*)&Wh[nxt + wr * 132 + wc4 * 4] = h;
            *(uint4*)&Wl[nxt + wr * 132 + wc4 * 4] = l;
            tfsplit(v1.x, h.x, l.x); tfsplit(v1.y, h.y, l.y);
            tfsplit(v1.z, h.z, l.z); tfsplit(v1.w, h.w, l.w);
            *(uint4*)&Wh[nxt + (wr + 8) * 132 + wc4 * 4] = h;
            *(uint4*)&Wl[nxt + (wr + 8) * 132 + wc4 * 4] = l;
            __syncthreads();
        }
    }

    int r0 = row0 + wm + gid, r1 = r0 + 8;
    float s0 = (r0 < n) ? g_dis[r0] : 0.f;
    float s1 = (r1 < n) ? g_dis[r1] : 0.f;
#pragma unroll
    for (int t = 0; t < 8; t++) {
        int col = wn + t * 8 + tig * 2;
        if (r0 < n) *(float2*)&g_xw1[(size_t)r0 * 128 + col] = make_float2(c[t].x * s0, c[t].y * s0);
        if (r1 < n) *(float2*)&g_xw1[(size_t)r1 * 128 + col] = make_float2(c[t].z * s1, c[t].w * s1);
    }
}

// ---- gather 1: acc1[d] = dis[d]*(xw1'[d] + sum xw1'[s]) --------
// 2 warps per dst (half row each, float2/lane), 8-deep batched loads.
__global__ void k_gather1(int n) {
    int w    = (blockIdx.x * blockDim.x + threadIdx.x) >> 5;
    int d    = w >> 1;
    if (d >= n) return;
    int half = w & 1;
    int lane = threadIdx.x & 31;
    int foff = half * 32 + lane;

    int   cnt = min(g_cnt[d], CAP);
    float dd  = g_dis[d];

    float2 acc = __ldg(&((const float2*)(g_xw1 + (size_t)d * 128))[foff]);

    const int* es = g_esrc + (size_t)d * CAP;
    int i = 0;
    for (; i + 8 <= cnt; i += 8) {
        int s[8];
#pragma unroll
        for (int j = 0; j < 8; j++) s[j] = __ldg(&es[i + j]);
#pragma unroll
        for (int j = 0; j < 8; j++) {
            float2 u = __ldg(&((const float2*)(g_xw1 + (size_t)s[j] * 128))[foff]);
            acc.x += u.x; acc.y += u.y;
        }
    }
    for (; i < cnt; i++) {
        int s = __ldg(&es[i]);
        float2 u = __ldg(&((const float2*)(g_xw1 + (size_t)s * 128))[foff]);
        acc.x += u.x; acc.y += u.y;
    }
    acc.x *= dd; acc.y *= dd;
    __stcs(&((float2*)(g_acc1 + (size_t)d * 128))[foff], acc);
}

// ---- GEMM 2 (3xTF32, double-buffered W): xw2' = (relu(acc1+b1)@W2)*dis ----
// dyn smem: As fp32 64x132 | Wh u32 [2][16x68] | Wl u32 [2][16x68] | b1s (52224 B)
#define CHUNK2 (16 * 68)
#define GEMM2_SMEM ((64 * 132 + 4 * CHUNK2 + 128) * 4)
__global__ void k_gemm2(const float* __restrict__ W2, const float* __restrict__ b1, int n) {
    extern __shared__ unsigned char dyn[];
    float*    As  = (float*)dyn;                      // 64*132
    unsigned* Wh  = (unsigned*)(As + 64 * 132);       // [2][16*68]
    unsigned* Wl  = Wh + 2 * CHUNK2;                  // [2][16*68]
    float*    b1s = (float*)(Wl + 2 * CHUNK2);        // 128
    int tid  = threadIdx.x;
    int lane = tid & 31, warp = tid >> 5;
    int wm = (warp & 3) * 16;
    int wn = (warp >> 2) * 32;          // 0 or 32
    int row0 = blockIdx.x * 64;
    int gid = lane >> 2, tig = lane & 3;

    if (tid < 128) b1s[tid] = b1[tid];
    __syncthreads();

    const float4* a4 = (const float4*)g_acc1;
#pragma unroll
    for (int i = 0; i < 8; i++) {
        int idx = tid + i * 256;
        int r = idx >> 5, c4 = idx & 31;
        int row = row0 + r;
        float4 v = (row < n) ? __ldcs(&a4[(size_t)row * 32 + c4])
                             : make_float4(0.f, 0.f, 0.f, 0.f);
        v.x = fmaxf(v.x + b1s[c4 * 4 + 0], 0.f);
        v.y = fmaxf(v.y + b1s[c4 * 4 + 1], 0.f);
        v.z = fmaxf(v.z + b1s[c4 * 4 + 2], 0.f);
        v.w = fmaxf(v.w + b1s[c4 * 4 + 3], 0.f);
        *(float4*)&As[r * 132 + c4 * 4] = v;
    }

    float4 c[4];
#pragma unroll
    for (int t = 0; t < 4; t++) c[t] = make_float4(0.f, 0.f, 0.f, 0.f);

    const float4* W4 = (const float4*)W2;
    int wr = tid >> 4, wc4 = tid & 15;   // 16x16 float4s = 256 threads, 1 each

    // prologue: chunk 0 -> buf 0
    {
        float4 v = __ldg(&W4[(size_t)wr * 16 + wc4]);
        uint4 h, l;
        tfsplit(v.x, h.x, l.x); tfsplit(v.y, h.y, l.y);
        tfsplit(v.z, h.z, l.z); tfsplit(v.w, h.w, l.w);
        *(uint4*)&Wh[wr * 68 + wc4 * 4] = h;
        *(uint4*)&Wl[wr * 68 + wc4 * 4] = l;
    }
    __syncthreads();

    for (int kc = 0; kc < 8; kc++) {
        int cur = (kc & 1) * CHUNK2;
        int nxt = ((kc + 1) & 1) * CHUNK2;
        float4 v;
        if (kc < 7)
            v = __ldg(&W4[(size_t)((kc + 1) * 16 + wr) * 16 + wc4]);
#pragma unroll
        for (int ks = 0; ks < 2; ks++) {
            int k0 = kc * 16 + ks * 8;
            int kk = ks * 8;
            unsigned ah[4], al[4];
            tfsplit(As[(wm + gid)     * 132 + k0 + tig],     ah[0], al[0]);
            tfsplit(As[(wm + gid + 8) * 132 + k0 + tig],     ah[1], al[1]);
            tfsplit(As[(wm + gid)     * 132 + k0 + tig + 4], ah[2], al[2]);
            tfsplit(As[(wm + gid + 8) * 132 + k0 + tig + 4], ah[3], al[3]);
#pragma unroll
            for (int t = 0; t < 4; t++) {
                int nn = wn + t * 8 + gid;
                unsigned bh0 = Wh[cur + (kk + tig)     * 68 + nn];
                unsigned bh1 = Wh[cur + (kk + tig + 4) * 68 + nn];
                unsigned bl0 = Wl[cur + (kk + tig)     * 68 + nn];
                unsigned bl1 = Wl[cur + (kk + tig + 4) * 68 + nn];
                mma_tf32(c[t], al[0], al[1], al[2], al[3], bh0, bh1);
                mma_tf32(c[t], ah[0], ah[1], ah[2], ah[3], bl0, bl1);
                mma_tf32(c[t], ah[0], ah[1], ah[2], ah[3], bh0, bh1);
            }
        }
        if (kc < 7) {
            uint4 h, l;
            tfsplit(v.x, h.x, l.x); tfsplit(v.y, h.y, l.y);
            tfsplit(v.z, h.z, l.z); tfsplit(v.w, h.w, l.w);
            *(uint4*)&Wh[nxt + wr * 68 + wc4 * 4] = h;
            *(uint4*)&Wl[nxt + wr * 68 + wc4 * 4] = l;
            __syncthreads();
        }
    }

    int r0 = row0 + wm + gid, r1 = r0 + 8;
    float s0 = (r0 < n) ? g_dis[r0] : 0.f;
    float s1 = (r1 < n) ? g_dis[r1] : 0.f;
#pragma unroll
    for (int t = 0; t < 4; t++) {
        int col = wn + t * 8 + tig * 2;
        if (r0 < n) *(float2*)&g_xw2[(size_t)r0 * 64 + col] = make_float2(c[t].x * s0, c[t].y * s0);
        if (r1 < n) *(float2*)&g_xw2[(size_t)r1 * 64 + col] = make_float2(c[t].z * s1, c[t].w * s1);
    }
}

// ---- gather 2 + pool: pooled[batch[d]] += relu(dd*(self+sum) + b2) --------
__global__ void k_gather2(const int* __restrict__ batch, const float* __restrict__ b2, int n) {
    int d    = (blockIdx.x * blockDim.x + threadIdx.x) >> 5;
    int lane = threadIdx.x & 31;
    if (d >= n) return;
    int   cnt = min(g_cnt[d], CAP);
    float dd  = g_dis[d];

    float2 acc = __ldg(&((const float2*)(g_xw2 + (size_t)d * 64))[lane]);

    const int* es = g_esrc + (size_t)d * CAP;
    int i = 0;
    for (; i + 8 <= cnt; i += 8) {
        int s[8];
#pragma unroll
        for (int j = 0; j < 8; j++) s[j] = __ldg(&es[i + j]);
#pragma unroll
        for (int j = 0; j < 8; j++) {
            float2 u = __ldg(&((const float2*)(g_xw2 + (size_t)s[j] * 64))[lane]);
            acc.x += u.x; acc.y += u.y;
        }
    }
    for (; i < cnt; i++) {
        int s = __ldg(&es[i]);
        float2 u = __ldg(&((const float2*)(g_xw2 + (size_t)s * 64))[lane]);
        acc.x += u.x; acc.y += u.y;
    }
    float2 b = __ldg(&((const float2*)b2)[lane]);
    float a0 = fmaxf(acc.x * dd + b.x, 0.f);
    float a1 = fmaxf(acc.y * dd + b.y, 0.f);
    int g = __ldg(&batch[d]);
    red_add_v2(&g_pooled[g * 64 + lane * 2], a0, a1);
}

// ---------------- BN statistics: 256 threads = 64 feat x 4 groups ----------
__global__ void k_bnstats() {
    __shared__ float ssum[256], ssq[256];
    int f   = threadIdx.x & 63;
    int grp = threadIdx.x >> 6;
    float s = 0.f, q = 0.f;
    for (int g = grp; g < NUM_GRAPHS; g += 4) {
        float v = g_pooled[g * 64 + f];
        s += v; q += v * v;
    }
    ssum[threadIdx.x] = s; ssq[threadIdx.x] = q;
    __syncthreads();
    if (grp == 0) {
        s = ssum[f] + ssum[f + 64] + ssum[f + 128] + ssum[f + 192];
        q = ssq [f] + ssq [f + 64] + ssq [f + 128] + ssq [f + 192];
        float m   = s * (1.0f / NUM_GRAPHS);
        float var = q * (1.0f / NUM_GRAPHS) - m * m;
        g_mean[f] = m;
        g_rstd[f] = rsqrtf(var + BN_EPS);
    }
}

// ---------------- head: BN affine + MLP; write (out, h) --------------------
__global__ void k_head(const float* __restrict__ gamma, const float* __restrict__ beta,
                       const float* __restrict__ Wo1,   const float* __restrict__ bo1,
                       const float* __restrict__ Wo2,   const float* __restrict__ bo2,
                       float* __restrict__ out) {
    int g = blockIdx.x * blockDim.x + threadIdx.x;
    if (g >= NUM_GRAPHS) return;
    float hid[24];
#pragma unroll
    for (int j = 0; j < 24; j++) hid[j] = __ldg(&bo1[j]);

    float* hout = out + NUM_GRAPHS + (size_t)g * 64;   // h = pooled (stop_gradient)
    for (int f = 0; f < 64; f++) {
        float p = g_pooled[g * 64 + f];
        hout[f] = p;
        float xn = (p - g_mean[f]) * g_rstd[f] * __ldg(&gamma[f]) + __ldg(&beta[f]);
#pragma unroll
        for (int j = 0; j < 24; j++)
            hid[j] += xn * __ldg(&Wo1[f * 24 + j]);
    }
    float o = __ldg(&bo2[0]);
#pragma unroll
    for (int j = 0; j < 24; j++)
        o += fmaxf(hid[j], 0.f) * __ldg(&Wo2[j]);
    out[g] = o;
}

// ---------------- launch ----------------
extern "C" void kernel_launch(void* const* d_in, const int* in_sizes, int n_in,
                              void* d_out, int out_size) {
    const float* x     = (const float*)d_in[0];
    const int*   ei    = (const int*)d_in[1];
    const int*   batch = (const int*)d_in[2];
    const float* W1    = (const float*)d_in[3];
    const float* b1    = (const float*)d_in[4];
    const float* W2    = (const float*)d_in[5];
    const float* b2    = (const float*)d_in[6];
    const float* gamma = (const float*)d_in[7];
    const float* beta  = (const float*)d_in[8];
    const float* Wo1   = (const float*)d_in[9];
    const float* bo1   = (const float*)d_in[10];
    const float* Wo2   = (const float*)d_in[11];
    const float* bo2   = (const float*)d_in[12];

    int N = in_sizes[0] / F1;
    int E = in_sizes[1] / 2;
    const int* src = ei;
    const int* dst = ei + E;
    float* out = (float*)d_out;

    static bool attr_done = false;
    if (!attr_done) {
        cudaFuncSetAttribute(k_gemm1, cudaFuncAttributeMaxDynamicSharedMemorySize, GEMM1_SMEM);
        cudaFuncSetAttribute(k_gemm2, cudaFuncAttributeMaxDynamicSharedMemorySize, GEMM2_SMEM);
        attr_done = true;
    }

    void* cnt_ptr = nullptr;
    cudaGetSymbolAddress(&cnt_ptr, g_cnt);
    cudaMemsetAsync(cnt_ptr, 0, NUM_NODES * sizeof(int));

    k_fill2  <<<(E + 255) / 256, 256>>>(src, dst, E);                   // idx 0
    k_dis    <<<(N + 255) / 256, 256>>>(N);                             // idx 1
    k_zero   <<<(NUM_GRAPHS * F2 + 255) / 256, 256>>>();                // idx 2
    k_gemm1  <<<(N + 63) / 64, 256, GEMM1_SMEM>>>(x, W1, N);            // idx 3 <- profiled
    k_gather1<<<(N + 3) / 4, 256>>>(N);
    k_gemm2  <<<(N + 63) / 64, 256, GEMM2_SMEM>>>(W2, b1, N);
    k_gather2<<<(N + 7) / 8, 256>>>(batch, b2, N);
    k_bnstats<<<1, 256>>>();
    k_head<<<(NUM_GRAPHS + 127) / 128, 128>>>(gamma, beta, Wo1, bo1, Wo2, bo2, out);
}

// round 15
// speedup vs baseline: 1.0202x; 1.0202x over previous
#include <cuda_runtime.h>

#define NUM_NODES  100000
#define NUM_GRAPHS 512
#define CAP 96                 // max in-degree slots (Poisson(16) tail: overflow ~1e-20)
#define F1 128
#define F2 64
#define BN_EPS 1e-5f

// ---------------- scratch (static device globals; no allocation) ----------------
__device__ __align__(16) int   g_cnt [NUM_NODES];          // in-degree (excl self)
__device__ __align__(16) int   g_esrc[NUM_NODES * CAP];    // bucket CSR: src ids per dst
__device__ __align__(16) float g_dis [NUM_NODES];
__device__ __align__(16) float g_xw1 [NUM_NODES * F1];     // pre-scaled by dis[row]
__device__ __align__(16) float g_acc1[NUM_NODES * F1];
__device__ __align__(16) float g_xw2 [NUM_NODES * F2];     // pre-scaled by dis[row]
__device__ __align__(16) float g_pooled[NUM_GRAPHS * F2];
__device__ __align__(16) float g_mean[F2];
__device__ __align__(16) float g_rstd[F2];

__device__ __forceinline__ void red_add_v2(float* p, float x, float y) {
    asm volatile("red.global.add.v2.f32 [%0], {%1,%2};"
                 :: "l"(p), "f"(x), "f"(y) : "memory");
}

__device__ __forceinline__ unsigned f2tf(float f) {
    unsigned u;
    asm("cvt.rna.tf32.f32 %0, %1;" : "=r"(u) : "f"(f));
    return u;
}
// split f into tf32 hi + tf32 lo (3xTF32 scheme)
__device__ __forceinline__ void tfsplit(float f, unsigned& hi, unsigned& lo) {
    hi = f2tf(f);
    lo = f2tf(f - __uint_as_float(hi));
}

__device__ __forceinline__ void mma_tf32(float4& c,
    unsigned a0, unsigned a1, unsigned a2, unsigned a3,
    unsigned b0, unsigned b1)
{
    asm volatile(
        "mma.sync.aligned.m16n8k8.row.col.f32.tf32.tf32.f32 "
        "{%0,%1,%2,%3}, {%4,%5,%6,%7}, {%8,%9}, {%0,%1,%2,%3};"
        : "+f"(c.x), "+f"(c.y), "+f"(c.z), "+f"(c.w)
        : "r"(a0), "r"(a1), "r"(a2), "r"(a3), "r"(b0), "r"(b1));
}

// -------- fused count + bucket fill: 1 edge per thread (latency-bound) -----
__global__ void k_fill2(const int* __restrict__ src, const int* __restrict__ dst, int E) {
    int e = blockIdx.x * blockDim.x + threadIdx.x;
    if (e < E) {
        int d = __ldg(&dst[e]);
        int s = __ldg(&src[e]);
        int slot = atomicAdd(&g_cnt[d], 1);
        if (slot < CAP) g_esrc[(size_t)d * CAP + slot] = s;
    }
}

// ---------------- dis = rsqrt(deg+1) ----------------
__global__ void k_dis(int n) {
    int i = blockIdx.x * blockDim.x + threadIdx.x;
    if (i < n) g_dis[i] = rsqrtf((float)(g_cnt[i] + 1));
}

// ---------------- zero pooled (kernel keeps gemm1 at profile idx 3) --------
__global__ void k_zero() {
    int i = blockIdx.x * blockDim.x + threadIdx.x;
    if (i < NUM_GRAPHS * F2) g_pooled[i] = 0.0f;
}

// ---- GEMM 1 (3xTF32, 2m x 4n warps, double-buffered W) --------------------
// dyn smem: As fp32 64x132 | Wh u32 [2][16x132] | Wl u32 [2][16x132]  (67584 B)
#define CHUNK1 (16 * 132)
#define GEMM1_SMEM ((64 * 132 + 4 * CHUNK1) * 4)
__global__ void k_gemm1(const float* __restrict__ x, const float* __restrict__ W, int n) {
    extern __shared__ unsigned char dyn[];
    float*    As = (float*)dyn;                       // 64*132
    unsigned* Wh = (unsigned*)(As + 64 * 132);        // [2][16*132]
    unsigned* Wl = Wh + 2 * CHUNK1;                   // [2][16*132]
    int tid  = threadIdx.x;
    int lane = tid & 31, warp = tid >> 5;
    int wm = (warp & 1) * 32;           // 2 m-warps: rows [wm, wm+32)
    int wn = (warp >> 1) * 32;          // 4 n-warps: cols [wn, wn+32)
    int row0 = blockIdx.x * 64;
    int gid = lane >> 2, tig = lane & 3;

    const float4* x4 = (const float4*)x;
#pragma unroll
    for (int i = 0; i < 8; i++) {
        int idx = tid + i * 256;        // 0..2047 float4s
        int r = idx >> 5, c4 = idx & 31;
        int row = row0 + r;
        float4 v = (row < n) ? __ldcs(&x4[(size_t)row * 32 + c4])
                             : make_float4(0.f, 0.f, 0.f, 0.f);
        *(float4*)&As[r * 132 + c4 * 4] = v;
    }

    float4 c[2][4];                     // [m-pair][n-tile]
#pragma unroll
    for (int p = 0; p < 2; p++)
#pragma unroll
        for (int t = 0; t < 4; t++) c[p][t] = make_float4(0.f, 0.f, 0.f, 0.f);

    const float4* W4 = (const float4*)W;
    int wr = tid >> 5, wc4 = tid & 31;  // W-chunk load coords (rows wr, wr+8)

    // prologue: chunk 0 -> buf 0
    {
        float4 v0 = __ldg(&W4[(size_t)wr * 32 + wc4]);
        float4 v1 = __ldg(&W4[(size_t)(wr + 8) * 32 + wc4]);
        uint4 h, l;
        tfsplit(v0.x, h.x, l.x); tfsplit(v0.y, h.y, l.y);
        tfsplit(v0.z, h.z, l.z); tfsplit(v0.w, h.w, l.w);
        *(uint4*)&Wh[wr * 132 + wc4 * 4] = h;
        *(uint4*)&Wl[wr * 132 + wc4 * 4] = l;
        tfsplit(v1.x, h.x, l.x); tfsplit(v1.y, h.y, l.y);
        tfsplit(v1.z, h.z, l.z); tfsplit(v1.w, h.w, l.w);
        *(uint4*)&Wh[(wr + 8) * 132 + wc4 * 4] = h;
        *(uint4*)&Wl[(wr + 8) * 132 + wc4 * 4] = l;
    }
    __syncthreads();

    for (int kc = 0; kc < 8; kc++) {
        int cur = (kc & 1) * CHUNK1;
        int nxt = ((kc + 1) & 1) * CHUNK1;
        float4 v0, v1;
        if (kc < 7) {   // prefetch next chunk to regs
            v0 = __ldg(&W4[(size_t)((kc + 1) * 16 + wr) * 32 + wc4]);
            v1 = __ldg(&W4[(size_t)((kc + 1) * 16 + wr + 8) * 32 + wc4]);
        }
#pragma unroll
        for (int ks = 0; ks < 2; ks++) {
            int k0 = kc * 16 + ks * 8;
            int kk = ks * 8;
            unsigned ah[2][4], al[2][4];
#pragma unroll
            for (int p = 0; p < 2; p++) {
                int rb = wm + p * 16;
                tfsplit(As[(rb + gid)     * 132 + k0 + tig],     ah[p][0], al[p][0]);
                tfsplit(As[(rb + gid + 8) * 132 + k0 + tig],     ah[p][1], al[p][1]);
                tfsplit(As[(rb + gid)     * 132 + k0 + tig + 4], ah[p][2], al[p][2]);
                tfsplit(As[(rb + gid + 8) * 132 + k0 + tig + 4], ah[p][3], al[p][3]);
            }
#pragma unroll
            for (int t = 0; t < 4; t++) {
                int nn = wn + t * 8 + gid;
                unsigned bh0 = Wh[cur + (kk + tig)     * 132 + nn];
                unsigned bh1 = Wh[cur + (kk + tig + 4) * 132 + nn];
                unsigned bl0 = Wl[cur + (kk + tig)     * 132 + nn];
                unsigned bl1 = Wl[cur + (kk + tig + 4) * 132 + nn];
#pragma unroll
                for (int p = 0; p < 2; p++) {
                    mma_tf32(c[p][t], al[p][0], al[p][1], al[p][2], al[p][3], bh0, bh1);
                    mma_tf32(c[p][t], ah[p][0], ah[p][1], ah[p][2], ah[p][3], bl0, bl1);
                    mma_tf32(c[p][t], ah[p][0], ah[p][1], ah[p][2], ah[p][3], bh0, bh1);
                }
            }
        }
        if (kc < 7) {
            uint4 h, l;
            tfsplit(v0.x, h.x, l.x); tfsplit(v0.y, h.y, l.y);
            tfsplit(v0.z, h.z, l.z); tfsplit(v0.w, h.w, l.w);
            *(uint4*)&Wh[nxt + wr * 132 + wc4 * 4] = h;
            *(uint4*)&Wl[nxt + wr * 132 + wc4 * 4] = l;
            tfsplit(v1.x, h.x, l.x); tfsplit(v1.y, h.y, l.y);
            tfsplit(v1.z, h.z, l.z); tfsplit(v1.w, h.w, l.w);
            *(uint4*)&Wh[nxt + (wr + 8) * 132 + wc4 * 4] = h;
            *(uint4*)&Wl[nxt + (wr + 8) * 132 + wc4 * 4] = l;
            __syncthreads();
        }
    }

#pragma unroll
    for (int p = 0; p < 2; p++) {
        int r0 = row0 + wm + p * 16 + gid, r1 = r0 + 8;
        float s0 = (r0 < n) ? g_dis[r0] : 0.f;
        float s1 = (r1 < n) ? g_dis[r1] : 0.f;
#pragma unroll
        for (int t = 0; t < 4; t++) {
            int col = wn + t * 8 + tig * 2;
            if (r0 < n) *(float2*)&g_xw1[(size_t)r0 * 128 + col] = make_float2(c[p][t].x * s0, c[p][t].y * s0);
            if (r1 < n) *(float2*)&g_xw1[(size_t)r1 * 128 + col] = make_float2(c[p][t].z * s1, c[p][t].w * s1);
        }
    }
}

// ---- gather 1: acc1[d] = dis[d]*(xw1'[d] + sum xw1'[s]) --------
__global__ void k_gather1(int n) {
    int w    = (blockIdx.x * blockDim.x + threadIdx.x) >> 5;
    int d    = w >> 1;
    if (d >= n) return;
    int half = w & 1;
    int lane = threadIdx.x & 31;
    int foff = half * 32 + lane;

    int   cnt = min(g_cnt[d], CAP);
    float dd  = g_dis[d];

    float2 acc = __ldg(&((const float2*)(g_xw1 + (size_t)d * 128))[foff]);

    const int* es = g_esrc + (size_t)d * CAP;
    int i = 0;
    for (; i + 8 <= cnt; i += 8) {
        int s[8];
#pragma unroll
        for (int j = 0; j < 8; j++) s[j] = __ldg(&es[i + j]);
#pragma unroll
        for (int j = 0; j < 8; j++) {
            float2 u = __ldg(&((const float2*)(g_xw1 + (size_t)s[j] * 128))[foff]);
            acc.x += u.x; acc.y += u.y;
        }
    }
    for (; i < cnt; i++) {
        int s = __ldg(&es[i]);
        float2 u = __ldg(&((const float2*)(g_xw1 + (size_t)s * 128))[foff]);
        acc.x += u.x; acc.y += u.y;
    }
    acc.x *= dd; acc.y *= dd;
    __stcs(&((float2*)(g_acc1 + (size_t)d * 128))[foff], acc);
}

// ---- GEMM 2 (3xTF32, 2m x 4n warps, double-buffered W) --------------------
// dyn smem: As fp32 64x132 | Wh u32 [2][16x68] | Wl u32 [2][16x68] | b1s (52224 B)
#define CHUNK2 (16 * 68)
#define GEMM2_SMEM ((64 * 132 + 4 * CHUNK2 + 128) * 4)
__global__ void k_gemm2(const float* __restrict__ W2, const float* __restrict__ b1, int n) {
    extern __shared__ unsigned char dyn[];
    float*    As  = (float*)dyn;                      // 64*132
    unsigned* Wh  = (unsigned*)(As + 64 * 132);       // [2][16*68]
    unsigned* Wl  = Wh + 2 * CHUNK2;                  // [2][16*68]
    float*    b1s = (float*)(Wl + 2 * CHUNK2);        // 128
    int tid  = threadIdx.x;
    int lane = tid & 31, warp = tid >> 5;
    int wm = (warp & 1) * 32;           // 2 m-warps
    int wn = (warp >> 1) * 16;          // 4 n-warps x 16 cols
    int row0 = blockIdx.x * 64;
    int gid = lane >> 2, tig = lane & 3;

    if (tid < 128) b1s[tid] = b1[tid];
    __syncthreads();

    const float4* a4 = (const float4*)g_acc1;
#pragma unroll
    for (int i = 0; i < 8; i++) {
        int idx = tid + i * 256;
        int r = idx >> 5, c4 = idx & 31;
        int row = row0 + r;
        float4 v = (row < n) ? __ldcs(&a4[(size_t)row * 32 + c4])
                             : make_float4(0.f, 0.f, 0.f, 0.f);
        v.x = fmaxf(v.x + b1s[c4 * 4 + 0], 0.f);
        v.y = fmaxf(v.y + b1s[c4 * 4 + 1], 0.f);
        v.z = fmaxf(v.z + b1s[c4 * 4 + 2], 0.f);
        v.w = fmaxf(v.w + b1s[c4 * 4 + 3], 0.f);
        *(float4*)&As[r * 132 + c4 * 4] = v;
    }

    float4 c[2][2];
#pragma unroll
    for (int p = 0; p < 2; p++)
#pragma unroll
        for (int t = 0; t < 2; t++) c[p][t] = make_float4(0.f, 0.f, 0.f, 0.f);

    const float4* W4 = (const float4*)W2;
    int wr = tid >> 4, wc4 = tid & 15;   // 16x16 float4s = 256 threads, 1 each

    // prologue: chunk 0 -> buf 0
    {
        float4 v = __ldg(&W4[(size_t)wr * 16 + wc4]);
        uint4 h, l;
        tfsplit(v.x, h.x, l.x); tfsplit(v.y, h.y, l.y);
        tfsplit(v.z, h.z, l.z); tfsplit(v.w, h.w, l.w);
        *(uint4*)&Wh[wr * 68 + wc4 * 4] = h;
        *(uint4*)&Wl[wr * 68 + wc4 * 4] = l;
    }
    __syncthreads();

    for (int kc = 0; kc < 8; kc++) {
        int cur = (kc & 1) * CHUNK2;
        int nxt = ((kc + 1) & 1) * CHUNK2;
        float4 v;
        if (kc < 7)
            v = __ldg(&W4[(size_t)((kc + 1) * 16 + wr) * 16 + wc4]);
#pragma unroll
        for (int ks = 0; ks < 2; ks++) {
            int k0 = kc * 16 + ks * 8;
            int kk = ks * 8;
            unsigned ah[2][4], al[2][4];
#pragma unroll
            for (int p = 0; p < 2; p++) {
                int rb = wm + p * 16;
                tfsplit(As[(rb + gid)     * 132 + k0 + tig],     ah[p][0], al[p][0]);
                tfsplit(As[(rb + gid + 8) * 132 + k0 + tig],     ah[p][1], al[p][1]);
                tfsplit(As[(rb + gid)     * 132 + k0 + tig + 4], ah[p][2], al[p][2]);
                tfsplit(As[(rb + gid + 8) * 132 + k0 + tig + 4], ah[p][3], al[p][3]);
            }
#pragma unroll
            for (int t = 0; t < 2; t++) {
                int nn = wn + t * 8 + gid;
                unsigned bh0 = Wh[cur + (kk + tig)     * 68 + nn];
                unsigned bh1 = Wh[cur + (kk + tig + 4) * 68 + nn];
                unsigned bl0 = Wl[cur + (kk + tig)     * 68 + nn];
                unsigned bl1 = Wl[cur + (kk + tig + 4) * 68 + nn];
#pragma unroll
                for (int p = 0; p < 2; p++) {
                    mma_tf32(c[p][t], al[p][0], al[p][1], al[p][2], al[p][3], bh0, bh1);
                    mma_tf32(c[p][t], ah[p][0], ah[p][1], ah[p][2], ah[p][3], bl0, bl1);
                    mma_tf32(c[p][t], ah[p][0], ah[p][1], ah[p][2], ah[p][3], bh0, bh1);
                }
            }
        }
        if (kc < 7) {
            uint4 h, l;
            tfsplit(v.x, h.x, l.x); tfsplit(v.y, h.y, l.y);
            tfsplit(v.z, h.z, l.z); tfsplit(v.w, h.w, l.w);
            *(uint4*)&Wh[nxt + wr * 68 + wc4 * 4] = h;
            *(uint4*)&Wl[nxt + wr * 68 + wc4 * 4] = l;
            __syncthreads();
        }
    }

#pragma unroll
    for (int p = 0; p < 2; p++) {
        int r0 = row0 + wm + p * 16 + gid, r1 = r0 + 8;
        float s0 = (r0 < n) ? g_dis[r0] : 0.f;
        float s1 = (r1 < n) ? g_dis[r1] : 0.f;
#pragma unroll
        for (int t = 0; t < 2; t++) {
            int col = wn + t * 8 + tig * 2;
            if (r0 < n) *(float2*)&g_xw2[(size_t)r0 * 64 + col] = make_float2(c[p][t].x * s0, c[p][t].y * s0);
            if (r1 < n) *(float2*)&g_xw2[(size_t)r1 * 64 + col] = make_float2(c[p][t].z * s1, c[p][t].w * s1);
        }
    }
}

// ---- gather 2 + pool: pooled[batch[d]] += relu(dd*(self+sum) + b2) --------
__global__ void k_gather2(const int* __restrict__ batch, const float* __restrict__ b2, int n) {
    int d    = (blockIdx.x * blockDim.x + threadIdx.x) >> 5;
    int lane = threadIdx.x & 31;
    if (d >= n) return;
    int   cnt = min(g_cnt[d], CAP);
    float dd  = g_dis[d];

    float2 acc = __ldg(&((const float2*)(g_xw2 + (size_t)d * 64))[lane]);

    const int* es = g_esrc + (size_t)d * CAP;
    int i = 0;
    for (; i + 8 <= cnt; i += 8) {
        int s[8];
#pragma unroll
        for (int j = 0; j < 8; j++) s[j] = __ldg(&es[i + j]);
#pragma unroll
        for (int j = 0; j < 8; j++) {
            float2 u = __ldg(&((const float2*)(g_xw2 + (size_t)s[j] * 64))[lane]);
            acc.x += u.x; acc.y += u.y;
        }
    }
    for (; i < cnt; i++) {
        int s = __ldg(&es[i]);
        float2 u = __ldg(&((const float2*)(g_xw2 + (size_t)s * 64))[lane]);
        acc.x += u.x; acc.y += u.y;
    }
    float2 b = __ldg(&((const float2*)b2)[lane]);
    float a0 = fmaxf(acc.x * dd + b.x, 0.f);
    float a1 = fmaxf(acc.y * dd + b.y, 0.f);
    int g = __ldg(&batch[d]);
    red_add_v2(&g_pooled[g * 64 + lane * 2], a0, a1);
}

// ---------------- BN statistics: 256 threads = 64 feat x 4 groups ----------
__global__ void k_bnstats() {
    __shared__ float ssum[256], ssq[256];
    int f   = threadIdx.x & 63;
    int grp = threadIdx.x >> 6;
    float s = 0.f, q = 0.f;
    for (int g = grp; g < NUM_GRAPHS; g += 4) {
        float v = g_pooled[g * 64 + f];
        s += v; q += v * v;
    }
    ssum[threadIdx.x] = s; ssq[threadIdx.x] = q;
    __syncthreads();
    if (grp == 0) {
        s = ssum[f] + ssum[f + 64] + ssum[f + 128] + ssum[f + 192];
        q = ssq [f] + ssq [f + 64] + ssq [f + 128] + ssq [f + 192];
        float m   = s * (1.0f / NUM_GRAPHS);
        float var = q * (1.0f / NUM_GRAPHS) - m * m;
        g_mean[f] = m;
        g_rstd[f] = rsqrtf(var + BN_EPS);
    }
}

// ---------------- head: BN affine + MLP; write (out, h) --------------------
__global__ void k_head(const float* __restrict__ gamma, const float* __restrict__ beta,
                       const float* __restrict__ Wo1,   const float* __restrict__ bo1,
                       const float* __restrict__ Wo2,   const float* __restrict__ bo2,
                       float* __restrict__ out) {
    int g = blockIdx.x * blockDim.x + threadIdx.x;
    if (g >= NUM_GRAPHS) return;
    float hid[24];
#pragma unroll
    for (int j = 0; j < 24; j++) hid[j] = __ldg(&bo1[j]);

    float* hout = out + NUM_GRAPHS + (size_t)g * 64;   // h = pooled (stop_gradient)
    for (int f = 0; f < 64; f++) {
        float p = g_pooled[g * 64 + f];
        hout[f] = p;
        float xn = (p - g_mean[f]) * g_rstd[f] * __ldg(&gamma[f]) + __ldg(&beta[f]);
#pragma unroll
        for (int j = 0; j < 24; j++)
            hid[j] += xn * __ldg(&Wo1[f * 24 + j]);
    }
    float o = __ldg(&bo2[0]);
#pragma unroll
    for (int j = 0; j < 24; j++)
        o += fmaxf(hid[j], 0.f) * __ldg(&Wo2[j]);
    out[g] = o;
}

// ---------------- launch ----------------
extern "C" void kernel_launch(void* const* d_in, const int* in_sizes, int n_in,
                              void* d_out, int out_size) {
    const float* x     = (const float*)d_in[0];
    const int*   ei    = (const int*)d_in[1];
    const int*   batch = (const int*)d_in[2];
    const float* W1    = (const float*)d_in[3];
    const float* b1    = (const float*)d_in[4];
    const float* W2    = (const float*)d_in[5];
    const float* b2    = (const float*)d_in[6];
    const float* gamma = (const float*)d_in[7];
    const float* beta  = (const float*)d_in[8];
    const float* Wo1   = (const float*)d_in[9];
    const float* bo1   = (const float*)d_in[10];
    const float* Wo2   = (const float*)d_in[11];
    const float* bo2   = (const float*)d_in[12];

    int N = in_sizes[0] / F1;
    int E = in_sizes[1] / 2;
    const int* src = ei;
    const int* dst = ei + E;
    float* out = (float*)d_out;

    static bool attr_done = false;
    if (!attr_done) {
        cudaFuncSetAttribute(k_gemm1, cudaFuncAttributeMaxDynamicSharedMemorySize, GEMM1_SMEM);
        cudaFuncSetAttribute(k_gemm2, cudaFuncAttributeMaxDynamicSharedMemorySize, GEMM2_SMEM);
        attr_done = true;
    }

    void* cnt_ptr = nullptr;
    cudaGetSymbolAddress(&cnt_ptr, g_cnt);
    cudaMemsetAsync(cnt_ptr, 0, NUM_NODES * sizeof(int));

    k_fill2  <<<(E + 255) / 256, 256>>>(src, dst, E);                   // idx 0
    k_dis    <<<(N + 255) / 256, 256>>>(N);                             // idx 1
    k_zero   <<<(NUM_GRAPHS * F2 + 255) / 256, 256>>>();                // idx 2
    k_gemm1  <<<(N + 63) / 64, 256, GEMM1_SMEM>>>(x, W1, N);            // idx 3 <- profiled
    k_gather1<<<(N + 3) / 4, 256>>>(N);
    k_gemm2  <<<(N + 63) / 64, 256, GEMM2_SMEM>>>(W2, b1, N);
    k_gather2<<<(N + 7) / 8, 256>>>(batch, b2, N);
    k_bnstats<<<1, 256>>>();
    k_head<<<(NUM_GRAPHS + 127) / 128, 128>>>(gamma, beta, Wo1, bo1, Wo2, bo2, out);
}